// round 1
// baseline (speedup 1.0000x reference)
#include <cuda_runtime.h>

// CASSI forward gather kernel.
// y[m, c] = sum_{l=0..63, 0<=c-l<N} x[m, c-l, l] * ca[m, c-l]
//
// x  : (1, 1024, 1024, 64) float32  -> 256 MB, read exactly once
// ca : (1, 1024, 1024, 1)  float32
// y  : (1, 1024, 1087, 1)  float32
//
// Coalescing: each thread rotates its l-iteration start by (c & 63) so that at
// every step j, lanes c..c+31 of a warp read 32 *consecutive* floats of x
// (same n-row, consecutive l), i.e. 1-2 fully-used 128B transactions.

#define MM   1024
#define NN   1024
#define LL   64
#define OUTC (NN + LL - 1)   // 1087
#define TC   256             // output columns per block

__global__ __launch_bounds__(TC)
void cassi_gather_kernel(const float* __restrict__ x,
                         const float* __restrict__ ca,
                         float* __restrict__ y)
{
    const int m   = blockIdx.y;
    const int c0  = blockIdx.x * TC;
    const int tid = threadIdx.x;
    const int c   = c0 + tid;                 // output column this thread owns

    // ca values needed: n in [c0-63, c0+TC-1]
    __shared__ float s_ca[TC + LL - 1];
    const int nbase = c0 - (LL - 1);
    for (int i = tid; i < TC + LL - 1; i += TC) {
        const int n = nbase + i;
        s_ca[i] = (n >= 0 && n < NN) ? ca[m * NN + n] : 0.0f;
    }
    __syncthreads();

    const float* xrow = x + (size_t)m * (NN * LL);
    const int lstart = c & (LL - 1);
    float acc = 0.0f;

    if (c0 >= (LL - 1) && (c0 + TC - 1) <= (NN - 1)) {
        // Interior fast path: every n = c - l is in [0, N) — no predicates.
        #pragma unroll
        for (int j = 0; j < LL; ++j) {
            const int l = (lstart + j) & (LL - 1);
            const int n = c - l;
            acc = fmaf(xrow[n * LL + l], s_ca[n - nbase], acc);
        }
    } else {
        // Edge blocks (first and last c-tiles): guarded.
        #pragma unroll
        for (int j = 0; j < LL; ++j) {
            const int l = (lstart + j) & (LL - 1);
            const int n = c - l;
            if (n >= 0 && n < NN)
                acc = fmaf(xrow[n * LL + l], s_ca[n - nbase], acc);
        }
    }

    if (c < OUTC)
        y[(size_t)m * OUTC + c] = acc;
}

extern "C" void kernel_launch(void* const* d_in, const int* in_sizes, int n_in,
                              void* d_out, int out_size)
{
    const float* x  = (const float*)d_in[0];   // (1, M, N, L) float32
    const float* ca = (const float*)d_in[1];   // (1, M, N, 1) float32
    float* y        = (float*)d_out;           // (1, M, N+L-1, 1) float32

    dim3 grid((OUTC + TC - 1) / TC, MM);
    cassi_gather_kernel<<<grid, TC>>>(x, ca, y);
}